// round 5
// baseline (speedup 1.0000x reference)
#include <cuda_runtime.h>
#include <cuda_fp16.h>
#include <cstdint>

#define B_  32
#define T_  512
#define D_  512
#define E_  8
#define H_  2048

// ---------------------------------------------------------------------------
// Device scratch
// ---------------------------------------------------------------------------
__device__ int    g_chosen[B_];
__device__ float  g_pool_part[B_ * 32 * D_];              // 2 MB
__device__ __half g_x_h[(size_t)B_ * T_ * D_];            // 16 MB
__device__ __half g_h_h[(size_t)B_ * T_ * H_];            // 64 MB
__device__ __half g_W1T[(size_t)E_ * D_ * H_];            // 16 MB  [E][H][D]
__device__ __half g_W2T[(size_t)E_ * H_ * D_];            // 16 MB  [E][D][H]

// ---------------------------------------------------------------------------
// PTX helpers (sm_80-baseline only)
// ---------------------------------------------------------------------------
__device__ __forceinline__ uint32_t smem_to_u32(const void* p) {
    uint32_t a;
    asm("{ .reg .u64 t; cvta.to.shared.u64 t, %1; cvt.u32.u64 %0, t; }"
        : "=r"(a) : "l"(p));
    return a;
}

__device__ __forceinline__ void cp16(uint32_t dst, const void* src) {
    asm volatile("cp.async.cg.shared.global [%0], [%1], 16;"
                 :: "r"(dst), "l"(src));
}
#define CP_COMMIT() asm volatile("cp.async.commit_group;" ::: "memory")
#define CP_WAIT1()  asm volatile("cp.async.wait_group 1;"  ::: "memory")

__device__ __forceinline__ void ldsm4(uint32_t* d, uint32_t addr) {
    asm volatile("ldmatrix.sync.aligned.m8n8.x4.shared.b16 {%0,%1,%2,%3}, [%4];"
                 : "=r"(d[0]), "=r"(d[1]), "=r"(d[2]), "=r"(d[3])
                 : "r"(addr));
}

__device__ __forceinline__ void mma16816(float* c, const uint32_t* a,
                                         const uint32_t* b) {
    asm volatile(
        "mma.sync.aligned.m16n8k16.row.col.f32.f16.f16.f32 "
        "{%0,%1,%2,%3}, {%4,%5,%6,%7}, {%8,%9}, {%0,%1,%2,%3};"
        : "+f"(c[0]), "+f"(c[1]), "+f"(c[2]), "+f"(c[3])
        : "r"(a[0]), "r"(a[1]), "r"(a[2]), "r"(a[3]),
          "r"(b[0]), "r"(b[1]));
}

// ---------------------------------------------------------------------------
// Kernel 1: convert x -> fp16, emit partial pooled sums
// ---------------------------------------------------------------------------
__global__ __launch_bounds__(256)
void xconv_pool_kernel(const float* __restrict__ x,
                       __half* __restrict__ xh,
                       float* __restrict__ pool_part)
{
    const int b  = blockIdx.x;
    const int tc = blockIdx.y;
    const int d0 = threadIdx.x * 2;

    float s0 = 0.0f, s1 = 0.0f;
    #pragma unroll 4
    for (int r = 0; r < 16; ++r) {
        const int t = tc * 16 + r;
        const size_t off = ((size_t)b * T_ + t) * D_ + d0;
        const float2 v = *reinterpret_cast<const float2*>(x + off);
        s0 += v.x; s1 += v.y;
        *reinterpret_cast<__half2*>(xh + off) =
            __halves2half2(__float2half_rn(v.x), __float2half_rn(v.y));
    }
    *reinterpret_cast<float2*>(pool_part + ((size_t)b * 32 + tc) * D_ + d0) =
        make_float2(s0, s1);
}

// ---------------------------------------------------------------------------
// Kernel 2: weight transpose+convert (W1 and W2 in one launch)
// ---------------------------------------------------------------------------
__global__ __launch_bounds__(256)
void wtrans_kernel(const float* __restrict__ W1,
                   const float* __restrict__ W2,
                   __half* __restrict__ W1T,
                   __half* __restrict__ W2T)
{
    __shared__ float s[32][33];
    const int which = blockIdx.z >> 3;          // 0: W1, 1: W2
    const int e     = blockIdx.z & 7;
    const int R = which ? H_ : D_;
    const int C = which ? D_ : H_;
    const int c0 = blockIdx.x * 32;
    const int r0 = blockIdx.y * 32;
    if (c0 >= C || r0 >= R) return;

    const float* src = (which ? W2 : W1) + (size_t)e * R * C;
    __half*      dst = (which ? W2T : W1T) + (size_t)e * R * C;

    #pragma unroll
    for (int k = 0; k < 4; ++k) {
        int idx = threadIdx.x + k * 256;
        int rr = idx >> 5, cc = idx & 31;
        s[rr][cc] = src[(size_t)(r0 + rr) * C + (c0 + cc)];
    }
    __syncthreads();
    #pragma unroll
    for (int k = 0; k < 4; ++k) {
        int idx = threadIdx.x + k * 256;
        int rr = idx >> 5, cc = idx & 31;
        dst[(size_t)(c0 + rr) * R + (r0 + cc)] = __float2half_rn(s[cc][rr]);
    }
}

// ---------------------------------------------------------------------------
// Kernel 3: router from pooled partials
// ---------------------------------------------------------------------------
__global__ __launch_bounds__(256)
void router_kernel(const float* __restrict__ pool_part,
                   const float* __restrict__ Wp,
                   const float* __restrict__ bp,
                   float* __restrict__ probs_out,
                   float* __restrict__ chosen_out)
{
    __shared__ float pooled[D_];
    __shared__ float logits[E_];
    const int b = blockIdx.x;

    for (int d = threadIdx.x; d < D_; d += 256) {
        float s = 0.0f;
        #pragma unroll
        for (int p = 0; p < 32; ++p)
            s += pool_part[((size_t)b * 32 + p) * D_ + d];
        pooled[d] = s * (1.0f / (float)T_);
    }
    __syncthreads();

    const int warp = threadIdx.x >> 5, lane = threadIdx.x & 31;
    {
        float s = 0.0f;
        for (int d = lane; d < D_; d += 32) s += pooled[d] * Wp[d * E_ + warp];
        #pragma unroll
        for (int off = 16; off > 0; off >>= 1)
            s += __shfl_down_sync(0xffffffffu, s, off);
        if (lane == 0) logits[warp] = s + bp[warp];
    }
    __syncthreads();

    if (threadIdx.x == 0) {
        float m = logits[0]; int arg = 0;
        #pragma unroll
        for (int e = 1; e < E_; ++e)
            if (logits[e] > m) { m = logits[e]; arg = e; }
        float ex[E_], sum = 0.0f;
        #pragma unroll
        for (int e = 0; e < E_; ++e) { ex[e] = expf(logits[e] - m); sum += ex[e]; }
        const float inv = 1.0f / sum;
        if (probs_out) {
            #pragma unroll
            for (int e = 0; e < E_; ++e) probs_out[b * E_ + e] = ex[e] * inv;
        }
        if (chosen_out) chosen_out[b] = (float)arg;
        g_chosen[b] = arg;
    }
}

// ---------------------------------------------------------------------------
// Kernel 4: batched expert GEMM, fp16 mma.sync, CUTLASS-style mainloop.
//   C[b] = act( A[b] @ BT[e]^T + bias[e] )
// CTA tile 128x256, 8 warps of 64x64, BK=64, 3-stage cp.async (48KB/stage),
// register double-buffered fragments, 1 CTA/SM.
// ---------------------------------------------------------------------------
#define STAGE_BYTES 49152          // A 16KB + B 32KB
#define GEMM_SMEM   (3 * STAGE_BYTES)

template <bool G1>   // true: relu + fp16 out; false: f32 out
__global__ __launch_bounds__(256, 1)
void moe_gemm_kernel(const __half* __restrict__ A,
                     const __half* __restrict__ BT,
                     const float* __restrict__ biasAll,
                     float* __restrict__ outF,
                     __half* __restrict__ outH,
                     int K, int Nt)
{
    extern __shared__ char smem[];
    const uint32_t sbase = smem_to_u32(smem);
    const int tid  = threadIdx.x;
    const int lane = tid & 31;
    const int wid  = tid >> 5;
    const int warp_m = wid & 1;          // 2 warps along M (64 each)
    const int warp_n = wid >> 1;         // 4 warps along N (64 each)

    const int b  = blockIdx.z;
    const int e  = g_chosen[b];
    const int m0 = blockIdx.y * 128;
    const int n0 = blockIdx.x * 256;

    const __half* Ag = A  + (size_t)b * T_ * K + (size_t)m0 * K;
    const __half* Bg = BT + (size_t)e * Nt * K + (size_t)n0 * K;

    // ldmatrix addressing constants (rows are 128B, XOR-16B swizzle on row%8)
    const int ltile = lane >> 3;
    const int lr    = lane & 7;
    const uint32_t xr = (uint32_t)lr << 4;
    const uint32_t baseA = (uint32_t)(warp_m * 64 + (ltile & 1) * 8 + lr) * 128u;
    const uint32_t kcA   = (uint32_t)(ltile >> 1) * 16u;
    const uint32_t baseB = (uint32_t)(warp_n * 64 + (ltile >> 1) * 8 + lr) * 128u;
    const uint32_t kcB   = (uint32_t)(ltile & 1) * 16u;

    float acc[4][8][4];
    #pragma unroll
    for (int mi = 0; mi < 4; ++mi)
        #pragma unroll
        for (int ni = 0; ni < 8; ++ni)
            #pragma unroll
            for (int i = 0; i < 4; ++i) acc[mi][ni][i] = 0.0f;

    const int KB = K >> 6;

    auto load_stage = [&](int stage_idx, int k0) {
        const uint32_t stg = sbase + (uint32_t)stage_idx * STAGE_BYTES;
        #pragma unroll
        for (int i = 0; i < 4; ++i) {               // A: 1024 quads
            const int q = tid + i * 256;
            const int row = q >> 3, j = q & 7;
            const uint32_t soff = (uint32_t)row * 128u +
                                  (((uint32_t)j * 16u) ^ (((uint32_t)(row & 7)) << 4));
            cp16(stg + soff, Ag + (size_t)row * K + k0 + j * 8);
        }
        #pragma unroll
        for (int i = 0; i < 8; ++i) {               // B: 2048 quads
            const int q = tid + i * 256;
            const int row = q >> 3, j = q & 7;
            const uint32_t soff = (uint32_t)row * 128u +
                                  (((uint32_t)j * 16u) ^ (((uint32_t)(row & 7)) << 4));
            cp16(stg + 16384u + soff, Bg + (size_t)row * K + k0 + j * 8);
        }
        CP_COMMIT();
    };

    load_stage(0, 0);
    if (KB > 1) load_stage(1, 64);
    else CP_COMMIT();

    uint32_t af[2][4][4], bf[2][8][2];

    auto load_frags = [&](int buf, uint32_t sA, uint32_t sB, int kk) {
        const uint32_t kA = ((uint32_t)(kk * 32) + kcA) ^ xr;
        const uint32_t kB = ((uint32_t)(kk * 32) + kcB) ^ xr;
        #pragma unroll
        for (int mi = 0; mi < 4; ++mi)
            ldsm4(af[buf][mi], sA + baseA + mi * 2048u + kA);
        #pragma unroll
        for (int pi = 0; pi < 4; ++pi) {
            uint32_t t4[4];
            ldsm4(t4, sB + baseB + pi * 2048u + kB);
            bf[buf][2*pi][0]   = t4[0]; bf[buf][2*pi][1]   = t4[1];
            bf[buf][2*pi+1][0] = t4[2]; bf[buf][2*pi+1][1] = t4[3];
        }
    };

    for (int kb = 0; kb < KB; ++kb) {
        CP_WAIT1();
        __syncthreads();
        // stage (kb+2)%3 was last read in iteration kb-1; barrier above makes
        // the overwrite safe. Always commit to keep wait_group accounting exact.
        if (kb + 2 < KB) load_stage((kb + 2) % 3, (kb + 2) << 6);
        else CP_COMMIT();

        const uint32_t stg = sbase + (uint32_t)(kb % 3) * STAGE_BYTES;
        const uint32_t sA = stg, sB = stg + 16384u;

        load_frags(0, sA, sB, 0);
        #pragma unroll
        for (int kk = 0; kk < 4; ++kk) {
            if (kk < 3) load_frags((kk + 1) & 1, sA, sB, kk + 1);
            #pragma unroll
            for (int mi = 0; mi < 4; ++mi)
                #pragma unroll
                for (int ni = 0; ni < 8; ++ni)
                    mma16816(acc[mi][ni], af[kk & 1][mi], bf[kk & 1][ni]);
        }
    }

    // ---- epilogue ----
    const int gm = m0 + warp_m * 64;
    const int gn = n0 + warp_n * 64;
    #pragma unroll
    for (int mi = 0; mi < 4; ++mi) {
        const int row0 = gm + mi * 16 + (lane >> 2);
        #pragma unroll
        for (int ni = 0; ni < 8; ++ni) {
            const int col = gn + ni * 8 + (lane & 3) * 2;
            const float2 bv = *reinterpret_cast<const float2*>(
                biasAll + (size_t)e * Nt + col);
            float v00 = acc[mi][ni][0] + bv.x;
            float v01 = acc[mi][ni][1] + bv.y;
            float v10 = acc[mi][ni][2] + bv.x;
            float v11 = acc[mi][ni][3] + bv.y;
            const size_t o0 = ((size_t)b * T_ + row0) * Nt + col;
            const size_t o1 = ((size_t)b * T_ + row0 + 8) * Nt + col;
            if (G1) {
                v00 = fmaxf(v00, 0.0f); v01 = fmaxf(v01, 0.0f);
                v10 = fmaxf(v10, 0.0f); v11 = fmaxf(v11, 0.0f);
                *reinterpret_cast<__half2*>(outH + o0) =
                    __halves2half2(__float2half_rn(v00), __float2half_rn(v01));
                *reinterpret_cast<__half2*>(outH + o1) =
                    __halves2half2(__float2half_rn(v10), __float2half_rn(v11));
            } else {
                *reinterpret_cast<float2*>(outF + o0) = make_float2(v00, v01);
                *reinterpret_cast<float2*>(outF + o1) = make_float2(v10, v11);
            }
        }
    }
}

// ---------------------------------------------------------------------------
// kernel_launch
// ---------------------------------------------------------------------------
extern "C" void kernel_launch(void* const* d_in, const int* in_sizes, int n_in,
                              void* d_out, int out_size)
{
    const float* x  = (const float*)d_in[0];
    const float* Wp = (const float*)d_in[1];
    const float* bp = (const float*)d_in[2];
    const float* W1 = (const float*)d_in[3];
    const float* b1 = (const float*)d_in[4];
    const float* W2 = (const float*)d_in[5];
    const float* b2 = (const float*)d_in[6];
    float* out = (float*)d_out;

    const long long FINAL_N = (long long)B_ * T_ * D_;
    float* probs_out  = nullptr;
    float* chosen_out = nullptr;
    if ((long long)out_size >= FINAL_N + (long long)B_ * E_)
        probs_out = out + FINAL_N;
    if ((long long)out_size >= FINAL_N + (long long)B_ * E_ + B_)
        chosen_out = out + FINAL_N + (long long)B_ * E_;

    __half *xh, *hh, *w1t, *w2t;
    float* pool_part;
    cudaGetSymbolAddress((void**)&xh, g_x_h);
    cudaGetSymbolAddress((void**)&hh, g_h_h);
    cudaGetSymbolAddress((void**)&w1t, g_W1T);
    cudaGetSymbolAddress((void**)&w2t, g_W2T);
    cudaGetSymbolAddress((void**)&pool_part, g_pool_part);

    cudaFuncSetAttribute(moe_gemm_kernel<true>,
                         cudaFuncAttributeMaxDynamicSharedMemorySize, GEMM_SMEM);
    cudaFuncSetAttribute(moe_gemm_kernel<false>,
                         cudaFuncAttributeMaxDynamicSharedMemorySize, GEMM_SMEM);

    // 1) x -> fp16 + pooled partials
    xconv_pool_kernel<<<dim3(B_, 32), 256>>>(x, xh, pool_part);

    // 2) router
    router_kernel<<<B_, 256>>>(pool_part, Wp, bp, probs_out, chosen_out);

    // 3) weight transpose+convert
    wtrans_kernel<<<dim3(H_ / 32, H_ / 32, E_ * 2), 256>>>(W1, W2, w1t, w2t);

    // 4) h = relu(x @ W1[e] + b1[e])  : M=512, N=2048, K=512
    moe_gemm_kernel<true><<<dim3(H_ / 256, T_ / 128, B_), 256, GEMM_SMEM>>>(
        xh, w1t, b1, nullptr, hh, D_, H_);

    // 5) final = h @ W2[e] + b2[e]    : M=512, N=512, K=2048
    moe_gemm_kernel<false><<<dim3(D_ / 256, T_ / 128, B_), 256, GEMM_SMEM>>>(
        hh, w2t, b2, out, nullptr, H_, D_);
}

// round 6
// speedup vs baseline: 1.0223x; 1.0223x over previous
#include <cuda_runtime.h>
#include <cuda_fp16.h>
#include <cstdint>

#define B_  32
#define T_  512
#define D_  512
#define E_  8
#define H_  2048

// ---------------------------------------------------------------------------
// Device scratch
// ---------------------------------------------------------------------------
__device__ int    g_chosen[B_];
__device__ float  g_pool_part[B_ * 32 * D_];              // 2 MB
__device__ __half g_x_h[(size_t)B_ * T_ * D_];            // 16 MB
__device__ __half g_h_h[(size_t)B_ * T_ * H_];            // 64 MB
__device__ __half g_W1T[(size_t)E_ * D_ * H_];            // 16 MB  [E][H][D]
__device__ __half g_W2T[(size_t)E_ * H_ * D_];            // 16 MB  [E][D][H]

// ---------------------------------------------------------------------------
// PTX helpers (sm_80-baseline only)
// ---------------------------------------------------------------------------
__device__ __forceinline__ uint32_t smem_to_u32(const void* p) {
    uint32_t a;
    asm("{ .reg .u64 t; cvta.to.shared.u64 t, %1; cvt.u32.u64 %0, t; }"
        : "=r"(a) : "l"(p));
    return a;
}

__device__ __forceinline__ void cp16(uint32_t dst, const void* src) {
    asm volatile("cp.async.cg.shared.global [%0], [%1], 16;"
                 :: "r"(dst), "l"(src));
}
#define CP_COMMIT() asm volatile("cp.async.commit_group;" ::: "memory")
#define CP_WAIT1()  asm volatile("cp.async.wait_group 1;"  ::: "memory")

__device__ __forceinline__ void ldsm4(uint32_t* d, uint32_t addr) {
    asm volatile("ldmatrix.sync.aligned.m8n8.x4.shared.b16 {%0,%1,%2,%3}, [%4];"
                 : "=r"(d[0]), "=r"(d[1]), "=r"(d[2]), "=r"(d[3])
                 : "r"(addr));
}

__device__ __forceinline__ void mma16816(float* c, const uint32_t* a,
                                         const uint32_t* b) {
    asm volatile(
        "mma.sync.aligned.m16n8k16.row.col.f32.f16.f16.f32 "
        "{%0,%1,%2,%3}, {%4,%5,%6,%7}, {%8,%9}, {%0,%1,%2,%3};"
        : "+f"(c[0]), "+f"(c[1]), "+f"(c[2]), "+f"(c[3])
        : "r"(a[0]), "r"(a[1]), "r"(a[2]), "r"(a[3]),
          "r"(b[0]), "r"(b[1]));
}

// ---------------------------------------------------------------------------
// Kernel 1: merged prep.
//   z==0: x -> fp16 + pooled partial sums   (x = b, y = t-chunk)
//   z==1: W1 [E][D][H] f32 -> W1T [E][H][D] fp16 (transpose+convert),
//         1024 groups of 8 (32x32) tiles
// ---------------------------------------------------------------------------
__global__ __launch_bounds__(256)
void prep_kernel(const float* __restrict__ x,
                 __half* __restrict__ xh,
                 float* __restrict__ pool_part,
                 const float* __restrict__ W1,
                 __half* __restrict__ W1T)
{
    if (blockIdx.z == 0) {
        const int b  = blockIdx.x;
        const int tc = blockIdx.y;
        const int d0 = threadIdx.x * 2;

        float s0 = 0.0f, s1 = 0.0f;
        #pragma unroll 4
        for (int r = 0; r < 16; ++r) {
            const int t = tc * 16 + r;
            const size_t off = ((size_t)b * T_ + t) * D_ + d0;
            const float2 v = *reinterpret_cast<const float2*>(x + off);
            s0 += v.x; s1 += v.y;
            *reinterpret_cast<__half2*>(xh + off) =
                __halves2half2(__float2half_rn(v.x), __float2half_rn(v.y));
        }
        *reinterpret_cast<float2*>(pool_part + ((size_t)b * 32 + tc) * D_ + d0) =
            make_float2(s0, s1);
        return;
    }

    // W1 transpose: R = D_ rows, C = H_ cols per expert -> dst [H][D]
    __shared__ float s[32][33];
    const int g = blockIdx.y * 32 + blockIdx.x;    // 0..1023
    #pragma unroll 1
    for (int i = 0; i < 8; ++i) {
        const int t = g * 8 + i;                   // 0..8191
        const int e  = t >> 10;
        const int w  = t & 1023;
        const int ct = w & 63;                     // 64 col tiles (H)
        const int rt = w >> 6;                     // 16 row tiles (D)
        const int c0 = ct * 32, r0 = rt * 32;
        const size_t sb = (size_t)e * D_ * H_;
        __syncthreads();
        #pragma unroll
        for (int k = 0; k < 4; ++k) {
            int idx = threadIdx.x + k * 256;
            int rr = idx >> 5, cc = idx & 31;
            s[rr][cc] = W1[sb + (size_t)(r0 + rr) * H_ + (c0 + cc)];
        }
        __syncthreads();
        #pragma unroll
        for (int k = 0; k < 4; ++k) {
            int idx = threadIdx.x + k * 256;
            int rr = idx >> 5, cc = idx & 31;
            W1T[sb + (size_t)(c0 + rr) * D_ + (r0 + cc)] =
                __float2half_rn(s[cc][rr]);
        }
    }
}

// ---------------------------------------------------------------------------
// Kernel 2: router from pooled partials. 512 threads: 1 d-column each.
// ---------------------------------------------------------------------------
__global__ __launch_bounds__(512)
void router_kernel(const float* __restrict__ pool_part,
                   const float* __restrict__ Wp,
                   const float* __restrict__ bp,
                   float* __restrict__ probs_out,
                   float* __restrict__ chosen_out)
{
    __shared__ float pooled[D_];
    __shared__ float logits[E_];
    const int b = blockIdx.x;
    const int d = threadIdx.x;

    {
        float s = 0.0f;
        #pragma unroll
        for (int p = 0; p < 32; ++p)
            s += pool_part[((size_t)b * 32 + p) * D_ + d];
        pooled[d] = s * (1.0f / (float)T_);
    }
    __syncthreads();

    const int warp = threadIdx.x >> 5, lane = threadIdx.x & 31;
    if (warp < E_) {
        float s = 0.0f;
        #pragma unroll
        for (int k = 0; k < 16; ++k) {
            const int dd = lane + k * 32;
            s += pooled[dd] * Wp[dd * E_ + warp];
        }
        #pragma unroll
        for (int off = 16; off > 0; off >>= 1)
            s += __shfl_down_sync(0xffffffffu, s, off);
        if (lane == 0) logits[warp] = s + bp[warp];
    }
    __syncthreads();

    if (threadIdx.x == 0) {
        float m = logits[0]; int arg = 0;
        #pragma unroll
        for (int e = 1; e < E_; ++e)
            if (logits[e] > m) { m = logits[e]; arg = e; }
        float ex[E_], sum = 0.0f;
        #pragma unroll
        for (int e = 0; e < E_; ++e) { ex[e] = expf(logits[e] - m); sum += ex[e]; }
        const float inv = 1.0f / sum;
        if (probs_out) {
            #pragma unroll
            for (int e = 0; e < E_; ++e) probs_out[b * E_ + e] = ex[e] * inv;
        }
        if (chosen_out) chosen_out[b] = (float)arg;
        g_chosen[b] = arg;
    }
}

// ---------------------------------------------------------------------------
// Kernel 3: batched expert GEMM (fp16 mma.sync) + fused W2 transpose blocks.
//   z <  32: C[b] = act( A[b] @ BT[e]^T + bias[e] ), CTA tile 128x128,
//            8 warps of 64x32, BK=64, 3-stage cp.async, 2 CTA/SM,
//            af-fragment double-buffered.
//   z >= 32 (G1 only): W2 [E][H][D] -> W2T [E][D][H] transpose+convert,
//            e = z-32, 16 (32x32) tiles per CTA.
// ---------------------------------------------------------------------------
#define STAGE_BYTES 32768          // A 16KB + B 16KB
#define GEMM_SMEM   (3 * STAGE_BYTES)

template <bool G1>   // true: relu + fp16 out; false: f32 out
__global__ __launch_bounds__(256, 2)
void moe_gemm_kernel(const __half* __restrict__ A,
                     const __half* __restrict__ BT,
                     const float* __restrict__ biasAll,
                     float* __restrict__ outF,
                     __half* __restrict__ outH,
                     int K, int Nt,
                     const float* __restrict__ W2src,
                     __half* __restrict__ W2T)
{
    extern __shared__ char smem[];

    if (G1 && blockIdx.z >= B_) {
        // ---- fused W2 transpose: R = H_ rows, C = D_ cols -> dst [D][H] ----
        float (*s)[33] = reinterpret_cast<float(*)[33]>(smem);
        const int e = blockIdx.z - B_;
        const int g = blockIdx.y * gridDim.x + blockIdx.x;  // 0..63
        const size_t sb = (size_t)e * H_ * D_;
        #pragma unroll 1
        for (int i = 0; i < 16; ++i) {
            const int t = g * 16 + i;         // 0..1023
            const int ct = t & 15;            // 16 col tiles (D)
            const int rt = t >> 4;            // 64 row tiles (H)
            const int c0 = ct * 32, r0 = rt * 32;
            __syncthreads();
            #pragma unroll
            for (int k = 0; k < 4; ++k) {
                int idx = threadIdx.x + k * 256;
                int rr = idx >> 5, cc = idx & 31;
                s[rr][cc] = W2src[sb + (size_t)(r0 + rr) * D_ + (c0 + cc)];
            }
            __syncthreads();
            #pragma unroll
            for (int k = 0; k < 4; ++k) {
                int idx = threadIdx.x + k * 256;
                int rr = idx >> 5, cc = idx & 31;
                W2T[sb + (size_t)(c0 + rr) * H_ + (r0 + cc)] =
                    __float2half_rn(s[cc][rr]);
            }
        }
        return;
    }

    const uint32_t sbase = smem_to_u32(smem);
    const int tid  = threadIdx.x;
    const int lane = tid & 31;
    const int wid  = tid >> 5;
    const int warp_m = wid & 1;          // 2 warps along M (64 each)
    const int warp_n = wid >> 1;         // 4 warps along N (32 each)

    const int b  = blockIdx.z;
    const int e  = g_chosen[b];
    const int m0 = blockIdx.y * 128;
    const int n0 = blockIdx.x * 128;

    const __half* Ag = A  + (size_t)b * T_ * K + (size_t)m0 * K;
    const __half* Bg = BT + (size_t)e * Nt * K + (size_t)n0 * K;

    const int ltile = lane >> 3;
    const int lr    = lane & 7;
    const uint32_t xr = (uint32_t)lr << 4;
    const uint32_t baseA = (uint32_t)(warp_m * 64 + (ltile & 1) * 8 + lr) * 128u;
    const uint32_t kcA   = (uint32_t)(ltile >> 1) * 16u;
    const uint32_t baseB = (uint32_t)(warp_n * 32 + (ltile >> 1) * 8 + lr) * 128u;
    const uint32_t kcB   = (uint32_t)(ltile & 1) * 16u;

    float acc[4][4][4];
    #pragma unroll
    for (int mi = 0; mi < 4; ++mi)
        #pragma unroll
        for (int ni = 0; ni < 4; ++ni)
            #pragma unroll
            for (int i = 0; i < 4; ++i) acc[mi][ni][i] = 0.0f;

    const int KB = K >> 6;

    auto load_stage = [&](int stage_idx, int k0) {
        const uint32_t stg = sbase + (uint32_t)stage_idx * STAGE_BYTES;
        #pragma unroll
        for (int i = 0; i < 4; ++i) {
            const int q = tid + i * 256;
            const int row = q >> 3, j = q & 7;
            const uint32_t soff = (uint32_t)row * 128u +
                                  (((uint32_t)j * 16u) ^ (((uint32_t)(row & 7)) << 4));
            cp16(stg + soff,          Ag + (size_t)row * K + k0 + j * 8);
            cp16(stg + 16384u + soff, Bg + (size_t)row * K + k0 + j * 8);
        }
        CP_COMMIT();
    };

    load_stage(0, 0);
    if (KB > 1) load_stage(1, 64);
    else CP_COMMIT();

    uint32_t af[2][4][4], bf[4][2];

    auto load_af = [&](int buf, uint32_t sA, int kk) {
        const uint32_t kA = ((uint32_t)(kk * 32) + kcA) ^ xr;
        #pragma unroll
        for (int mi = 0; mi < 4; ++mi)
            ldsm4(af[buf][mi], sA + baseA + mi * 2048u + kA);
    };
    auto load_bf = [&](uint32_t sB, int kk) {
        const uint32_t kB = ((uint32_t)(kk * 32) + kcB) ^ xr;
        #pragma unroll
        for (int pi = 0; pi < 2; ++pi) {
            uint32_t t4[4];
            ldsm4(t4, sB + baseB + pi * 2048u + kB);
            bf[2*pi][0]   = t4[0]; bf[2*pi][1]   = t4[1];
            bf[2*pi+1][0] = t4[2]; bf[2*pi+1][1] = t4[3];
        }
    };

    for (int kb = 0; kb < KB; ++kb) {
        CP_WAIT1();
        __syncthreads();
        if (kb + 2 < KB) load_stage((kb + 2) % 3, (kb + 2) << 6);
        else CP_COMMIT();

        const uint32_t stg = sbase + (uint32_t)(kb % 3) * STAGE_BYTES;
        const uint32_t sA = stg, sB = stg + 16384u;

        load_af(0, sA, 0);
        #pragma unroll
        for (int kk = 0; kk < 4; ++kk) {
            load_bf(sB, kk);
            if (kk < 3) load_af((kk + 1) & 1, sA, kk + 1);
            #pragma unroll
            for (int mi = 0; mi < 4; ++mi)
                #pragma unroll
                for (int ni = 0; ni < 4; ++ni)
                    mma16816(acc[mi][ni], af[kk & 1][mi], bf[ni]);
        }
    }

    // ---- epilogue ----
    const int gm = m0 + warp_m * 64;
    const int gncol = n0 + warp_n * 32;
    #pragma unroll
    for (int mi = 0; mi < 4; ++mi) {
        const int row0 = gm + mi * 16 + (lane >> 2);
        #pragma unroll
        for (int ni = 0; ni < 4; ++ni) {
            const int col = gncol + ni * 8 + (lane & 3) * 2;
            const float2 bv = *reinterpret_cast<const float2*>(
                biasAll + (size_t)e * Nt + col);
            float v00 = acc[mi][ni][0] + bv.x;
            float v01 = acc[mi][ni][1] + bv.y;
            float v10 = acc[mi][ni][2] + bv.x;
            float v11 = acc[mi][ni][3] + bv.y;
            const size_t o0 = ((size_t)b * T_ + row0) * Nt + col;
            const size_t o1 = ((size_t)b * T_ + row0 + 8) * Nt + col;
            if (G1) {
                v00 = fmaxf(v00, 0.0f); v01 = fmaxf(v01, 0.0f);
                v10 = fmaxf(v10, 0.0f); v11 = fmaxf(v11, 0.0f);
                *reinterpret_cast<__half2*>(outH + o0) =
                    __halves2half2(__float2half_rn(v00), __float2half_rn(v01));
                *reinterpret_cast<__half2*>(outH + o1) =
                    __halves2half2(__float2half_rn(v10), __float2half_rn(v11));
            } else {
                *reinterpret_cast<float2*>(outF + o0) = make_float2(v00, v01);
                *reinterpret_cast<float2*>(outF + o1) = make_float2(v10, v11);
            }
        }
    }
}

// ---------------------------------------------------------------------------
// kernel_launch
// ---------------------------------------------------------------------------
extern "C" void kernel_launch(void* const* d_in, const int* in_sizes, int n_in,
                              void* d_out, int out_size)
{
    const float* x  = (const float*)d_in[0];
    const float* Wp = (const float*)d_in[1];
    const float* bp = (const float*)d_in[2];
    const float* W1 = (const float*)d_in[3];
    const float* b1 = (const float*)d_in[4];
    const float* W2 = (const float*)d_in[5];
    const float* b2 = (const float*)d_in[6];
    float* out = (float*)d_out;

    const long long FINAL_N = (long long)B_ * T_ * D_;
    float* probs_out  = nullptr;
    float* chosen_out = nullptr;
    if ((long long)out_size >= FINAL_N + (long long)B_ * E_)
        probs_out = out + FINAL_N;
    if ((long long)out_size >= FINAL_N + (long long)B_ * E_ + B_)
        chosen_out = out + FINAL_N + (long long)B_ * E_;

    __half *xh, *hh, *w1t, *w2t;
    float* pool_part;
    cudaGetSymbolAddress((void**)&xh, g_x_h);
    cudaGetSymbolAddress((void**)&hh, g_h_h);
    cudaGetSymbolAddress((void**)&w1t, g_W1T);
    cudaGetSymbolAddress((void**)&w2t, g_W2T);
    cudaGetSymbolAddress((void**)&pool_part, g_pool_part);

    cudaFuncSetAttribute(moe_gemm_kernel<true>,
                         cudaFuncAttributeMaxDynamicSharedMemorySize, GEMM_SMEM);
    cudaFuncSetAttribute(moe_gemm_kernel<false>,
                         cudaFuncAttributeMaxDynamicSharedMemorySize, GEMM_SMEM);

    // 1) merged prep: x->fp16 + pool partials (z=0), W1 transpose (z=1)
    prep_kernel<<<dim3(32, 32, 2), 256>>>(x, xh, pool_part, W1, w1t);

    // 2) router
    router_kernel<<<B_, 512>>>(pool_part, Wp, bp, probs_out, chosen_out);

    // 3) GEMM1 (z<32) + fused W2 transpose (z=32..39)
    //    h = relu(x @ W1[e] + b1[e]) : M=512, N=2048, K=512
    moe_gemm_kernel<true><<<dim3(H_ / 128, T_ / 128, B_ + 8), 256, GEMM_SMEM>>>(
        xh, w1t, b1, nullptr, hh, D_, H_, W2, w2t);

    // 4) GEMM2: final = h @ W2[e] + b2[e] : M=512, N=512, K=2048
    moe_gemm_kernel<false><<<dim3(D_ / 128, T_ / 128, B_), 256, GEMM_SMEM>>>(
        hh, w2t, b2, out, nullptr, H_, D_, nullptr, nullptr);
}